// round 14
// baseline (speedup 1.0000x reference)
#include <cuda_runtime.h>
#include <cstdint>

// AI4DEM coupling_backward: 3x3 tent-spline gather, 4096x4096 periodic grid.
// Inputs: xp, yp, x_grid(unused), y_grid(unused), vx, vy, Fx, Fy, mask
// Output: 5 planes [alpha, alpha_u, alpha_v, Fx, Fy], each 4096*4096 f32.
//
//   per tap: w = max(0,1-|xp_src - x_dst|) * max(0,1-|yp_src - y_dst|)
//   out     = mask_dst * VP * sum(w * field_src)     (mask at DESTINATION)
//
// R14: small-tile variant of R11 to break the 24-warp occupancy pin.
// Block = 128 threads, 128x4 output tile; each thread a 1x4 tile (3 src
// rows). Accumulators 40->20 regs and smem 36.7->21.6KB, so 8 blocks/SM
// (32 warps, 8-phase stagger) fit under __launch_bounds__(128,8).
// Costs ~27% more fp/LDS per output (weight sharing across 2 dst rows
// lost) -- paid from slack fma/L1 capacity to buy latency hiding.

#define NXD   4096
#define MASKW 4095

#define BLK_T    128          // threads per block
#define OUT_ROWS 4            // output rows per block
#define SRC_ROWS 6            // OUT_ROWS + 2 halo rows
#define ROWW     136          // 4 pad | 128 main | 4 pad  (floats)
#define ROWVECS  34           // float4s per field-row
#define VECS_PER_FIELD (SRC_ROWS * ROWVECS)   // 204
#define MK_VECS  (OUT_ROWS * 32)              // 128 float4s of mask

__device__ __forceinline__ void cpa16(uint32_t saddr, const float* g) {
    asm volatile("cp.async.cg.shared.global [%0], [%1], 16;\n"
                 :: "r"(saddr), "l"(g));
}

__device__ __forceinline__ float tent(float d) {
    return fmaxf(1.0f - fabsf(d), 0.0f);
}

__device__ __forceinline__ constexpr int kmin_of(int s) { return (s - 2 > 0) ? (s - 2) : 0; }
__device__ __forceinline__ constexpr int kmax_of(int s) { return (s < 3) ? s : 3; }

__global__ void __launch_bounds__(BLK_T, 8)
ai4dem_kernel(const float* __restrict__ xp, const float* __restrict__ yp,
              const float* __restrict__ vx, const float* __restrict__ vy,
              const float* __restrict__ Fx, const float* __restrict__ Fy,
              const float* __restrict__ mk, float* __restrict__ out)
{
    const float VP = 3.1415f / 6.0f;

    __shared__ float sm[6][SRC_ROWS][ROWW];   // 19,584 B
    __shared__ float smk[OUT_ROWS][128];      //  2,048 B   (total 21,632)

    const int t   = threadIdx.x;
    const int bx  = blockIdx.x & 31;          // 32 col-blocks
    const int by  = blockIdx.x >> 5;          // 1024 row-blocks
    const int xb0 = bx << 7;                  // block's first col
    const int y0b = by << 2;                  // block's first out row

    // ---- stage 6 fields x 6 rows x 136 cols + mask 4x128 via cp.async ----
    {
        const float* fptr[6] = {xp, yp, vx, vy, Fx, Fy};
        #pragma unroll
        for (int f = 0; f < 6; ++f) {
            const float* base = fptr[f];
            #pragma unroll
            for (int j = t; j < VECS_PER_FIELD; j += BLK_T) {
                int rr = j / ROWVECS;                 // 0..5
                int v  = j - rr * ROWVECS;            // 0..33
                int gy = (y0b - 1 + rr) & MASKW;
                int gx = (xb0 - 4 + (v << 2)) & MASKW;   // 16B-aligned, wraps whole
                uint32_t sa = (uint32_t)__cvta_generic_to_shared(&sm[f][rr][v << 2]);
                cpa16(sa, base + ((size_t)gy << 12) + gx);
            }
        }
        // mask: 4 rows x 128 cols, aligned, no halo
        #pragma unroll
        for (int j = t; j < MK_VECS; j += BLK_T) {
            int rr = j >> 5;                          // 0..3
            int v  = j & 31;                          // 0..31
            uint32_t sa = (uint32_t)__cvta_generic_to_shared(&smk[rr][v << 2]);
            cpa16(sa, mk + ((size_t)(y0b + rr) << 12) + xb0 + (v << 2));
        }
        asm volatile("cp.async.commit_group;\n" ::: "memory");
        asm volatile("cp.async.wait_group 0;\n" ::: "memory");
        __syncthreads();
    }

    // ---- compute: each thread a 1x4 output tile ----
    const int tx = t & 31;                    // col quad within block
    const int ty = t >> 5;                    // row within block (0..3)
    const int xl = tx << 2;                   // local col offset
    const int xb = xb0 + xl;                  // global base col
    const int y0 = y0b + ty;                  // global out row

    const float fy0 = (float)y0;
    const float xk0 = (float)xb;
    const float xdst[4] = {xk0, xk0 + 1.0f, xk0 + 2.0f, xk0 + 3.0f};

    float aA[4] = {0.f, 0.f, 0.f, 0.f};
    float aU[4] = {0.f, 0.f, 0.f, 0.f};
    float aV[4] = {0.f, 0.f, 0.f, 0.f};
    float aX[4] = {0.f, 0.f, 0.f, 0.f};
    float aY[4] = {0.f, 0.f, 0.f, 0.f};

    #pragma unroll
    for (int r = 0; r < 3; ++r) {             // src rows y0-1 .. y0+1
        const int sr = ty + r;                // smem row 0..5

        // coords -> weights (xp/yp regs die immediately)
        float ny[6];
        float nx[12];
        {
            float4 qx = *reinterpret_cast<const float4*>(&sm[0][sr][4 + xl]);
            float xl0 = sm[0][sr][3 + xl], xr0 = sm[0][sr][8 + xl];
            float4 qy = *reinterpret_cast<const float4*>(&sm[1][sr][4 + xl]);
            float yl0 = sm[1][sr][3 + xl], yr0 = sm[1][sr][8 + xl];
            float xps[6] = {xl0, qx.x, qx.y, qx.z, qx.w, xr0};
            float yps[6] = {yl0, qy.x, qy.y, qy.z, qy.w, yr0};
            int idx = 0;
            #pragma unroll
            for (int s = 0; s < 6; ++s) {
                ny[s] = tent(yps[s] - fy0);
                #pragma unroll
                for (int k = kmin_of(s); k <= kmax_of(s); ++k)
                    nx[idx++] = tent(xps[s] - xdst[k]);
            }
        }

        // vx / vy + alpha
        {
            float4 qu = *reinterpret_cast<const float4*>(&sm[2][sr][4 + xl]);
            float ul = sm[2][sr][3 + xl], ur = sm[2][sr][8 + xl];
            float4 qv = *reinterpret_cast<const float4*>(&sm[3][sr][4 + xl]);
            float vl = sm[3][sr][3 + xl], vr = sm[3][sr][8 + xl];
            float vxs[6] = {ul, qu.x, qu.y, qu.z, qu.w, ur};
            float vys[6] = {vl, qv.x, qv.y, qv.z, qv.w, vr};
            int idx = 0;
            #pragma unroll
            for (int s = 0; s < 6; ++s) {
                float n  = ny[s];
                float tu = n * vxs[s];
                float tv = n * vys[s];
                #pragma unroll
                for (int k = kmin_of(s); k <= kmax_of(s); ++k, ++idx) {
                    float w = nx[idx];
                    aA[k] = fmaf(w, n,  aA[k]);
                    aU[k] = fmaf(w, tu, aU[k]);
                    aV[k] = fmaf(w, tv, aV[k]);
                }
            }
        }

        // Fx / Fy
        {
            float4 qa = *reinterpret_cast<const float4*>(&sm[4][sr][4 + xl]);
            float al = sm[4][sr][3 + xl], ar = sm[4][sr][8 + xl];
            float4 qb = *reinterpret_cast<const float4*>(&sm[5][sr][4 + xl]);
            float bl = sm[5][sr][3 + xl], br = sm[5][sr][8 + xl];
            float fxs[6] = {al, qa.x, qa.y, qa.z, qa.w, ar};
            float fys[6] = {bl, qb.x, qb.y, qb.z, qb.w, br};
            int idx = 0;
            #pragma unroll
            for (int s = 0; s < 6; ++s) {
                float n   = ny[s];
                float txv = n * fxs[s];
                float tyv = n * fys[s];
                #pragma unroll
                for (int k = kmin_of(s); k <= kmax_of(s); ++k, ++idx) {
                    float w = nx[idx];
                    aX[k] = fmaf(w, txv, aX[k]);
                    aY[k] = fmaf(w, tyv, aY[k]);
                }
            }
        }
    }

    // ---- mask (from smem, staged) * VP, then store 5 planes ----
    const size_t P = (size_t)NXD * NXD;
    size_t o = ((size_t)y0 << 12) + xb;
    float4 mq = *reinterpret_cast<const float4*>(&smk[ty][xl]);
    float md[4] = {mq.x * VP, mq.y * VP, mq.z * VP, mq.w * VP};

    #pragma unroll
    for (int k = 0; k < 4; ++k) {
        aA[k] *= md[k]; aU[k] *= md[k]; aV[k] *= md[k];
        aX[k] *= md[k]; aY[k] *= md[k];
    }

    *reinterpret_cast<float4*>(out + o)         = make_float4(aA[0], aA[1], aA[2], aA[3]);
    *reinterpret_cast<float4*>(out + P + o)     = make_float4(aU[0], aU[1], aU[2], aU[3]);
    *reinterpret_cast<float4*>(out + 2 * P + o) = make_float4(aV[0], aV[1], aV[2], aV[3]);
    *reinterpret_cast<float4*>(out + 3 * P + o) = make_float4(aX[0], aX[1], aX[2], aX[3]);
    *reinterpret_cast<float4*>(out + 4 * P + o) = make_float4(aY[0], aY[1], aY[2], aY[3]);
}

extern "C" void kernel_launch(void* const* d_in, const int* in_sizes, int n_in,
                              void* d_out, int out_size)
{
    const float* xp = (const float*)d_in[0];
    const float* yp = (const float*)d_in[1];
    // d_in[2] = x_grid, d_in[3] = y_grid: analytic (x, y), not needed.
    const float* vx = (const float*)d_in[4];
    const float* vy = (const float*)d_in[5];
    const float* Fx = (const float*)d_in[6];
    const float* Fy = (const float*)d_in[7];
    const float* mk = (const float*)d_in[8];
    float* out = (float*)d_out;

    // 32 col-blocks x 1024 row-blocks; each block: 128 cols x 4 rows of output
    ai4dem_kernel<<<32 * 1024, BLK_T>>>(xp, yp, vx, vy, Fx, Fy, mk, out);
}

// round 15
// speedup vs baseline: 1.1636x; 1.1636x over previous
#include <cuda_runtime.h>
#include <cstdint>

// AI4DEM coupling_backward: 3x3 tent-spline gather, 4096x4096 periodic grid.
// Inputs: xp, yp, x_grid(unused), y_grid(unused), vx, vy, Fx, Fy, mask
// Output: 5 planes [alpha, alpha_u, alpha_v, Fx, Fy], each 4096*4096 f32.
//
//   per tap: w = max(0,1-|xp_src - x_dst|) * max(0,1-|yp_src - y_dst|)
//   out     = mask_dst * VP * sum(w * field_src)     (mask at DESTINATION)
//
// R15 = R11 (champion: cp.async staging 10x136x6 + 8x128 mask, one barrier,
// 2x4 outputs/thread, 6 blocks/SM) + __stcs streaming stores. The 320MB of
// output writes have zero reuse; evict-first keeps halo rows (re-read by
// neighbor blocks) L2-resident, protecting the DRAM-read compulsory floor.
// Single-variable change vs R11 per post-mortem discipline.

#define NXD   4096
#define MASKW 4095

#define BLK_T    128          // threads per block
#define OUT_ROWS 8            // output rows per block
#define SRC_ROWS 10           // OUT_ROWS + 2 halo rows
#define ROWW     136          // 4 pad | 128 main | 4 pad  (floats)
#define ROWVECS  34           // ROWW / 4 float4s per field-row
#define VECS_PER_FIELD (SRC_ROWS * ROWVECS)   // 340
#define MK_VECS  (OUT_ROWS * 32)              // 256 float4s of mask

__device__ __forceinline__ void cpa16(uint32_t saddr, const float* g) {
    asm volatile("cp.async.cg.shared.global [%0], [%1], 16;\n"
                 :: "r"(saddr), "l"(g));
}

__device__ __forceinline__ float tent(float d) {
    return fmaxf(1.0f - fabsf(d), 0.0f);
}

__device__ __forceinline__ constexpr int kmin_of(int s) { return (s - 2 > 0) ? (s - 2) : 0; }
__device__ __forceinline__ constexpr int kmax_of(int s) { return (s < 3) ? s : 3; }

__global__ void __launch_bounds__(BLK_T, 6)
ai4dem_kernel(const float* __restrict__ xp, const float* __restrict__ yp,
              const float* __restrict__ vx, const float* __restrict__ vy,
              const float* __restrict__ Fx, const float* __restrict__ Fy,
              const float* __restrict__ mk, float* __restrict__ out)
{
    const float VP = 3.1415f / 6.0f;

    __shared__ float sm[6][SRC_ROWS][ROWW];   // 32,640 B
    __shared__ float smk[OUT_ROWS][128];      //  4,096 B

    const int t   = threadIdx.x;
    const int bx  = blockIdx.x & 31;          // 32 col-blocks
    const int by  = blockIdx.x >> 5;          // 512 row-blocks
    const int xb0 = bx << 7;                  // block's first col
    const int y0b = by << 3;                  // block's first out row

    // ---- stage 6 fields x 10 rows x 136 cols + mask 8x128 via cp.async ----
    {
        const float* fptr[6] = {xp, yp, vx, vy, Fx, Fy};
        #pragma unroll
        for (int f = 0; f < 6; ++f) {
            const float* base = fptr[f];
            #pragma unroll
            for (int j = t; j < VECS_PER_FIELD; j += BLK_T) {
                int rr = j / ROWVECS;                 // 0..9
                int v  = j - rr * ROWVECS;            // 0..33
                int gy = (y0b - 1 + rr) & MASKW;
                int gx = (xb0 - 4 + (v << 2)) & MASKW;   // 16B-aligned, wraps whole
                uint32_t sa = (uint32_t)__cvta_generic_to_shared(&sm[f][rr][v << 2]);
                cpa16(sa, base + ((size_t)gy << 12) + gx);
            }
        }
        // mask: 8 rows x 128 cols, aligned, no halo
        #pragma unroll
        for (int j = t; j < MK_VECS; j += BLK_T) {
            int rr = j >> 5;                          // 0..7
            int v  = j & 31;                          // 0..31
            uint32_t sa = (uint32_t)__cvta_generic_to_shared(&smk[rr][v << 2]);
            cpa16(sa, mk + ((size_t)(y0b + rr) << 12) + xb0 + (v << 2));
        }
        asm volatile("cp.async.commit_group;\n" ::: "memory");
        asm volatile("cp.async.wait_group 0;\n" ::: "memory");
        __syncthreads();
    }

    // ---- compute: each thread a 2x4 output tile ----
    const int tx = t & 31;                    // col quad within block
    const int ty = t >> 5;                    // row pair within block (0..3)
    const int xl = tx << 2;                   // local col offset
    const int xb = xb0 + xl;                  // global base col
    const int y0 = y0b + (ty << 1);           // global first out row

    const float fy0 = (float)y0;
    const float fy1 = (float)(y0 + 1);
    const float xk0 = (float)xb;
    const float xdst[4] = {xk0, xk0 + 1.0f, xk0 + 2.0f, xk0 + 3.0f};

    float aA[2][4] = {{0.f,0.f,0.f,0.f},{0.f,0.f,0.f,0.f}};
    float aU[2][4] = {{0.f,0.f,0.f,0.f},{0.f,0.f,0.f,0.f}};
    float aV[2][4] = {{0.f,0.f,0.f,0.f},{0.f,0.f,0.f,0.f}};
    float aX[2][4] = {{0.f,0.f,0.f,0.f},{0.f,0.f,0.f,0.f}};
    float aY[2][4] = {{0.f,0.f,0.f,0.f},{0.f,0.f,0.f,0.f}};

    #pragma unroll
    for (int r = 0; r < 4; ++r) {             // src rows y0-1 .. y0+2
        const int sr = (ty << 1) + r;         // smem row 0..9

        // tent support: src row r reaches dst rows within distance 1
        const int dmin = (r == 3) ? 1 : 0;
        const int dmax = (r == 0) ? 0 : 1;

        // coords -> weights (xp/yp regs die immediately)
        float ny[2][6];
        float nx[12];
        {
            float4 qx = *reinterpret_cast<const float4*>(&sm[0][sr][4 + xl]);
            float xl0 = sm[0][sr][3 + xl], xr0 = sm[0][sr][8 + xl];
            float4 qy = *reinterpret_cast<const float4*>(&sm[1][sr][4 + xl]);
            float yl0 = sm[1][sr][3 + xl], yr0 = sm[1][sr][8 + xl];
            float xps[6] = {xl0, qx.x, qx.y, qx.z, qx.w, xr0};
            float yps[6] = {yl0, qy.x, qy.y, qy.z, qy.w, yr0};
            int idx = 0;
            #pragma unroll
            for (int s = 0; s < 6; ++s) {
                #pragma unroll
                for (int d = dmin; d <= dmax; ++d)
                    ny[d][s] = tent(yps[s] - (d ? fy1 : fy0));
                #pragma unroll
                for (int k = kmin_of(s); k <= kmax_of(s); ++k)
                    nx[idx++] = tent(xps[s] - xdst[k]);
            }
        }

        // vx / vy + alpha
        {
            float4 qu = *reinterpret_cast<const float4*>(&sm[2][sr][4 + xl]);
            float ul = sm[2][sr][3 + xl], ur = sm[2][sr][8 + xl];
            float4 qv = *reinterpret_cast<const float4*>(&sm[3][sr][4 + xl]);
            float vl = sm[3][sr][3 + xl], vr = sm[3][sr][8 + xl];
            float vxs[6] = {ul, qu.x, qu.y, qu.z, qu.w, ur};
            float vys[6] = {vl, qv.x, qv.y, qv.z, qv.w, vr};
            int idx = 0;
            #pragma unroll
            for (int s = 0; s < 6; ++s) {
                const int i0 = idx;
                #pragma unroll
                for (int d = dmin; d <= dmax; ++d) {
                    float n  = ny[d][s];
                    float tu = n * vxs[s];
                    float tv = n * vys[s];
                    int ii = i0;
                    #pragma unroll
                    for (int k = kmin_of(s); k <= kmax_of(s); ++k, ++ii) {
                        float w = nx[ii];
                        aA[d][k] = fmaf(w, n,  aA[d][k]);
                        aU[d][k] = fmaf(w, tu, aU[d][k]);
                        aV[d][k] = fmaf(w, tv, aV[d][k]);
                    }
                }
                idx += kmax_of(s) - kmin_of(s) + 1;
            }
        }

        // Fx / Fy
        {
            float4 qa = *reinterpret_cast<const float4*>(&sm[4][sr][4 + xl]);
            float al = sm[4][sr][3 + xl], ar = sm[4][sr][8 + xl];
            float4 qb = *reinterpret_cast<const float4*>(&sm[5][sr][4 + xl]);
            float bl = sm[5][sr][3 + xl], br = sm[5][sr][8 + xl];
            float fxs[6] = {al, qa.x, qa.y, qa.z, qa.w, ar};
            float fys[6] = {bl, qb.x, qb.y, qb.z, qb.w, br};
            int idx = 0;
            #pragma unroll
            for (int s = 0; s < 6; ++s) {
                const int i0 = idx;
                #pragma unroll
                for (int d = dmin; d <= dmax; ++d) {
                    float n   = ny[d][s];
                    float txv = n * fxs[s];
                    float tyv = n * fys[s];
                    int ii = i0;
                    #pragma unroll
                    for (int k = kmin_of(s); k <= kmax_of(s); ++k, ++ii) {
                        float w = nx[ii];
                        aX[d][k] = fmaf(w, txv, aX[d][k]);
                        aY[d][k] = fmaf(w, tyv, aY[d][k]);
                    }
                }
                idx += kmax_of(s) - kmin_of(s) + 1;
            }
        }
    }

    // ---- mask (from smem, staged) * VP, then stream-store 5 planes ----
    const size_t P = (size_t)NXD * NXD;
    #pragma unroll
    for (int d = 0; d < 2; ++d) {
        size_t o = ((size_t)(y0 + d) << 12) + xb;
        float4 mq = *reinterpret_cast<const float4*>(&smk[(ty << 1) + d][xl]);
        float md[4] = {mq.x * VP, mq.y * VP, mq.z * VP, mq.w * VP};

        #pragma unroll
        for (int k = 0; k < 4; ++k) {
            aA[d][k] *= md[k]; aU[d][k] *= md[k]; aV[d][k] *= md[k];
            aX[d][k] *= md[k]; aY[d][k] *= md[k];
        }

        __stcs(reinterpret_cast<float4*>(out + o),         make_float4(aA[d][0], aA[d][1], aA[d][2], aA[d][3]));
        __stcs(reinterpret_cast<float4*>(out + P + o),     make_float4(aU[d][0], aU[d][1], aU[d][2], aU[d][3]));
        __stcs(reinterpret_cast<float4*>(out + 2 * P + o), make_float4(aV[d][0], aV[d][1], aV[d][2], aV[d][3]));
        __stcs(reinterpret_cast<float4*>(out + 3 * P + o), make_float4(aX[d][0], aX[d][1], aX[d][2], aX[d][3]));
        __stcs(reinterpret_cast<float4*>(out + 4 * P + o), make_float4(aY[d][0], aY[d][1], aY[d][2], aY[d][3]));
    }
}

extern "C" void kernel_launch(void* const* d_in, const int* in_sizes, int n_in,
                              void* d_out, int out_size)
{
    const float* xp = (const float*)d_in[0];
    const float* yp = (const float*)d_in[1];
    // d_in[2] = x_grid, d_in[3] = y_grid: analytic (x, y), not needed.
    const float* vx = (const float*)d_in[4];
    const float* vy = (const float*)d_in[5];
    const float* Fx = (const float*)d_in[6];
    const float* Fy = (const float*)d_in[7];
    const float* mk = (const float*)d_in[8];
    float* out = (float*)d_out;

    // 32 col-blocks x 512 row-blocks; each block: 128 cols x 8 rows of output
    ai4dem_kernel<<<32 * 512, BLK_T>>>(xp, yp, vx, vy, Fx, Fy, mk, out);
}